// round 6
// baseline (speedup 1.0000x reference)
#include <cuda_runtime.h>

#define THREADS 128
#define PTS_PER_BLOCK 256   // 2 points per thread

// ---- shared-memory layout (floats): weights only ----
#define S_W1T   0        // [105][64]  bw1 transposed  (6720)
#define S_B1    6720     // [64]
#define S_W2T   6784     // [64][32]   bw2 transposed  (2048)
#define S_B2    8832     // [32]
#define S_V1T   8864     // [32][32]   vw1 transposed, pre-scaled by 1/3 (1024)
#define S_VB1   9888     // [32]
#define S_V2T   9920     // [32][32]   vw2 transposed (1024)
#define S_VB2   10944    // [32]
#define S_R1T   10976    // [96][32]   rw1 transposed (3072)
#define S_RB1   14048    // [32]
#define S_R2T   14080    // [32][16]   rw2 transposed (512)
#define S_RB2   14592    // [16]
#define S_RW3   14608    // [3][16]    rw3 as-is (48)
#define S_RB3   14656    // [4]
#define S_WEND  14660
#define SMEM_BYTES (S_WEND * 4)   // 58640 B -> 3 blocks/SM

#define P_CONST 524288
#define NGRP    (P_CONST / 64)    // warp pair-groups (64 pts each: 32 A + 32 B)

typedef unsigned long long ull;

// global scratch (module-static; allocation-free at kernel time)
__device__ float g_scr[(size_t)P_CONST * 105];               // input, interleaved [P/32][105][32]
__device__ ull   g1_scr[(size_t)NGRP * 64 * 32];             // g1: 64 ull slots x 32 lanes per group (134MB)
__device__ ull   x_scr[(size_t)NGRP * 3 * 32 * 32];          // x per view: 32 slots x 32 lanes (201MB)

__device__ __forceinline__ float elu1(float x) {
    return x > 0.f ? x : (__expf(x) - 1.f);
}
__device__ __forceinline__ void ffma2(ull &d, ull a, ull b) {
    asm("fma.rn.f32x2 %0, %1, %2, %0;" : "+l"(d) : "l"(a), "l"(b));
}
__device__ __forceinline__ ull bcast2(float c) {
    ull v; asm("mov.b64 %0, {%1, %2};" : "=l"(v) : "f"(c), "f"(c)); return v;
}
__device__ __forceinline__ ull pack2(float lo, float hi) {
    ull v; asm("mov.b64 %0, {%1, %2};" : "=l"(v) : "f"(lo), "f"(hi)); return v;
}
__device__ __forceinline__ void unpack2(ull v, float &lo, float &hi) {
    asm("mov.b64 {%0, %1}, %2;" : "=f"(lo), "=f"(hi) : "l"(v));
}

// dual-point FMA row: one weight load feeds both points (1 LDS.128 : 4 FFMA2)
template<int OUT>
__device__ __forceinline__ void fma_row2(ull* a, ull* b, const float* row, ull ca, ull cb) {
    const ulonglong2* wp = reinterpret_cast<const ulonglong2*>(row);
#pragma unroll
    for (int q = 0; q < OUT / 4; ++q) {
        ulonglong2 w = wp[q];
        ffma2(a[2 * q],     ca, w.x);
        ffma2(b[2 * q],     cb, w.x);
        ffma2(a[2 * q + 1], ca, w.y);
        ffma2(b[2 * q + 1], cb, w.y);
    }
}
template<int OUT>
__device__ __forceinline__ void load_bias2(ull* a, ull* b, const float* bp_) {
    const ulonglong2* bp = reinterpret_cast<const ulonglong2*>(bp_);
#pragma unroll
    for (int q = 0; q < OUT / 4; ++q) {
        ulonglong2 w = bp[q];
        a[2 * q] = w.x; a[2 * q + 1] = w.y;
        b[2 * q] = w.x; b[2 * q + 1] = w.y;
    }
}

// ================= K0: transpose input to [P/32][105][32] + emit rgb_in ==========
__global__ __launch_bounds__(256, 4)
void k_prep(const float* __restrict__ rgb, float* __restrict__ out_in, int P)
{
    __shared__ float st[32 * 105];
    const int g = blockIdx.x;             // point group (32 points)
    const int tid = threadIdx.x;

    const float4* src4 = reinterpret_cast<const float4*>(rgb + (size_t)g * 3360);
    float4* st4 = reinterpret_cast<float4*>(st);
#pragma unroll
    for (int i = tid; i < 840; i += 256) st4[i] = src4[i];
    __syncthreads();

    float* dst = g_scr + (size_t)g * 105 * 32;
#pragma unroll
    for (int i = tid; i < 3360; i += 256) {
        int j = i >> 5, lane = i & 31;
        dst[i] = st[lane * 105 + j];
    }
    for (int i = tid; i < 288; i += 256) {
        int pl = i / 9, r = i % 9, v = r / 3, k = r % 3;
        out_in[((size_t)g * 32 + pl) * 9 + r] = st[pl * 105 + v * 35 + k];
    }
}

// ================= K1: main fused MLP, 2 points/thread, 12 warps/SM ===============
__global__ __launch_bounds__(THREADS, 3)
void k_main(
    const float* __restrict__ bw1, const float* __restrict__ bb1,
    const float* __restrict__ bw2, const float* __restrict__ bb2,
    const float* __restrict__ vw1, const float* __restrict__ vb1,
    const float* __restrict__ vw2, const float* __restrict__ vb2,
    const float* __restrict__ rw1, const float* __restrict__ rb1,
    const float* __restrict__ rw2, const float* __restrict__ rb2,
    const float* __restrict__ rw3, const float* __restrict__ rb3,
    float* __restrict__ out_rgb, int P)
{
    extern __shared__ float s[];
    const int tid = threadIdx.x;

    // ---- stage weights (transposed) ----
    for (int i = tid; i < 6720; i += THREADS) { int k = i >> 6, j = i & 63; s[S_W1T + i] = bw1[j * 105 + k]; }
    for (int i = tid; i < 64;   i += THREADS) s[S_B1 + i] = bb1[i];
    for (int i = tid; i < 2048; i += THREADS) { int k = i >> 5, j = i & 31; s[S_W2T + i] = bw2[j * 64 + k]; }
    for (int i = tid; i < 32;   i += THREADS) s[S_B2 + i] = bb2[i];
    for (int i = tid; i < 1024; i += THREADS) { int k = i >> 5, j = i & 31; s[S_V1T + i] = vw1[j * 32 + k] * (1.f / 3.f); }
    for (int i = tid; i < 32;   i += THREADS) s[S_VB1 + i] = vb1[i];
    for (int i = tid; i < 1024; i += THREADS) { int k = i >> 5, j = i & 31; s[S_V2T + i] = vw2[j * 32 + k]; }
    for (int i = tid; i < 32;   i += THREADS) s[S_VB2 + i] = vb2[i];
    for (int i = tid; i < 3072; i += THREADS) { int k = i >> 5, j = i & 31; s[S_R1T + i] = rw1[j * 96 + k]; }
    for (int i = tid; i < 32;   i += THREADS) s[S_RB1 + i] = rb1[i];
    for (int i = tid; i < 512;  i += THREADS) { int k = i >> 4, j = i & 15; s[S_R2T + i] = rw2[j * 32 + k]; }
    for (int i = tid; i < 16;   i += THREADS) s[S_RB2 + i] = rb2[i];
    for (int i = tid; i < 48;   i += THREADS) s[S_RW3 + i] = rw3[i];
    for (int i = tid; i < 4;    i += THREADS) s[S_RB3 + i] = (i < 3) ? rb3[i] : 0.f;
    __syncthreads();

    const int lane = tid & 31;
    const int w    = tid >> 5;               // warp in block (0..3)
    const int p0 = blockIdx.x * PTS_PER_BLOCK + tid;   // point A
    const int p1 = p0 + THREADS;                        // point B
    // input: element j of point p at g_scr[(p>>5)*3360 + j*32 + (p&31)]
    const float* fA = g_scr + ((size_t)(blockIdx.x * 8 + w)) * 3360 + lane;
    const float* fB = fA + (size_t)4 * 3360;
#define FA(j) __ldg(fA + (j) * 32)
#define FB(j) __ldg(fB + (j) * 32)

    const size_t grp = (size_t)blockIdx.x * 4 + w;      // pair group (64 pts)
    ull* g1p = g1_scr + grp * 64 * 32 + lane;           // slot j at g1p[j*32]
    ull* xp  = x_scr  + grp * 3 * 32 * 32 + lane;       // view v slot j at xp[(v*32+j)*32]

    // ---- phase 0: stats + g1 = bb1 + W1[:,:70] @ [mean,var]; park in scratch ----
    {
        ull g1a[32], g1b[32];
        load_bias2<64>(g1a, g1b, s + S_B1);
#pragma unroll 5
        for (int k = 0; k < 35; ++k) {
            float aA = FA(k), bA = FA(35 + k), cA = FA(70 + k);
            float aB = FB(k), bB = FB(35 + k), cB = FB(70 + k);
            float mA = (aA + bA + cA) * (1.f / 3.f);
            float mB = (aB + bB + cB) * (1.f / 3.f);
            float qA = fmaf(-mA, mA, fmaf(aA, aA, fmaf(bA, bA, cA * cA)) * (1.f / 3.f));
            float qB = fmaf(-mB, mB, fmaf(aB, aB, fmaf(bB, bB, cB * cB)) * (1.f / 3.f));
            fma_row2<64>(g1a, g1b, s + S_W1T + k * 64,        bcast2(mA), bcast2(mB));
            fma_row2<64>(g1a, g1b, s + S_W1T + (35 + k) * 64, bcast2(qA), bcast2(qB));
        }
#pragma unroll
        for (int j = 0; j < 32; ++j) {
            g1p[j * 32]        = g1a[j];
            g1p[(32 + j) * 32] = g1b[j];
        }
    }

    // ---- per-view MLP: produce x_v = elu(h2) + elu(t2), park in scratch ----
#pragma unroll 1
    for (int v = 0; v < 3; ++v) {
        ull h2a[16], h2b[16];
        load_bias2<32>(h2a, h2b, s + S_B2);

        // layer1 (in column halves, init from parked g1) feeding layer2
#pragma unroll 1
        for (int h = 0; h < 2; ++h) {
            ull h1a[16], h1b[16];
#pragma unroll
            for (int j = 0; j < 16; ++j) {
                h1a[j] = g1p[(h * 16 + j) * 32];
                h1b[j] = g1p[(32 + h * 16 + j) * 32];
            }
#pragma unroll 5
            for (int k = 0; k < 35; ++k) {
                float ca = FA(v * 35 + k), cb = FB(v * 35 + k);
                fma_row2<32>(h1a, h1b, s + S_W1T + (70 + k) * 64 + h * 32,
                             bcast2(ca), bcast2(cb));
            }
#pragma unroll
            for (int i = 0; i < 16; ++i) {
                float alo, ahi, blo, bhi;
                unpack2(h1a[i], alo, ahi);
                unpack2(h1b[i], blo, bhi);
                fma_row2<32>(h2a, h2b, s + S_W2T + (h * 32 + 2 * i) * 32,
                             bcast2(elu1(alo)), bcast2(elu1(blo)));
                fma_row2<32>(h2a, h2b, s + S_W2T + (h * 32 + 2 * i + 1) * 32,
                             bcast2(elu1(ahi)), bcast2(elu1(bhi)));
            }
        }
        // h2e = elu(h2) in place
#pragma unroll
        for (int i = 0; i < 16; ++i) {
            float lo, hi;
            unpack2(h2a[i], lo, hi); h2a[i] = pack2(elu1(lo), elu1(hi));
            unpack2(h2b[i], lo, hi); h2b[i] = pack2(elu1(lo), elu1(hi));
        }

        // t1 = vb1 + (vw1/3) @ h2e
        ull t1a[16], t1b[16];
        load_bias2<32>(t1a, t1b, s + S_VB1);
#pragma unroll
        for (int i = 0; i < 16; ++i) {
            float alo, ahi, blo, bhi;
            unpack2(h2a[i], alo, ahi);
            unpack2(h2b[i], blo, bhi);
            fma_row2<32>(t1a, t1b, s + S_V1T + (2 * i) * 32,     bcast2(alo), bcast2(blo));
            fma_row2<32>(t1a, t1b, s + S_V1T + (2 * i + 1) * 32, bcast2(ahi), bcast2(bhi));
        }
        // park h2e (residual) in the x slot; h2 registers die here
#pragma unroll
        for (int j = 0; j < 16; ++j) {
            xp[(v * 32 + j) * 32]      = h2a[j];
            xp[(v * 32 + 16 + j) * 32] = h2b[j];
        }
        // t1e = elu(t1) in place
#pragma unroll
        for (int i = 0; i < 16; ++i) {
            float lo, hi;
            unpack2(t1a[i], lo, hi); t1a[i] = pack2(elu1(lo), elu1(hi));
            unpack2(t1b[i], lo, hi); t1b[i] = pack2(elu1(lo), elu1(hi));
        }

        // t2 = vb2 + vw2 @ t1e
        ull t2a[16], t2b[16];
        load_bias2<32>(t2a, t2b, s + S_VB2);
#pragma unroll
        for (int i = 0; i < 16; ++i) {
            float alo, ahi, blo, bhi;
            unpack2(t1a[i], alo, ahi);
            unpack2(t1b[i], blo, bhi);
            fma_row2<32>(t2a, t2b, s + S_V2T + (2 * i) * 32,     bcast2(alo), bcast2(blo));
            fma_row2<32>(t2a, t2b, s + S_V2T + (2 * i + 1) * 32, bcast2(ahi), bcast2(bhi));
        }

        // x = h2e + elu(t2): rmw the parked slot
#pragma unroll
        for (int j = 0; j < 16; ++j) {
            float tlo, thi, hlo, hhi;
            unpack2(t2a[j], tlo, thi);
            ull ha = xp[(v * 32 + j) * 32];
            unpack2(ha, hlo, hhi);
            xp[(v * 32 + j) * 32] = pack2(hlo + elu1(tlo), hhi + elu1(thi));

            unpack2(t2b[j], tlo, thi);
            ull hb = xp[(v * 32 + 16 + j) * 32];
            unpack2(hb, hlo, hhi);
            xp[(v * 32 + 16 + j) * 32] = pack2(hlo + elu1(tlo), hhi + elu1(thi));
        }
    }

    // ---- head: r1 = rb1 + rw1 @ x(96), from parked x ----
    ull r1a[16], r1b[16];
    load_bias2<32>(r1a, r1b, s + S_RB1);
#pragma unroll 1
    for (int v = 0; v < 3; ++v) {
#pragma unroll
        for (int j = 0; j < 16; ++j) {
            ull xa = xp[(v * 32 + j) * 32];
            ull xb = xp[(v * 32 + 16 + j) * 32];
            float alo, ahi, blo, bhi;
            unpack2(xa, alo, ahi);
            unpack2(xb, blo, bhi);
            fma_row2<32>(r1a, r1b, s + S_R1T + (v * 32 + 2 * j) * 32,
                         bcast2(alo), bcast2(blo));
            fma_row2<32>(r1a, r1b, s + S_R1T + (v * 32 + 2 * j + 1) * 32,
                         bcast2(ahi), bcast2(bhi));
        }
    }

    // r2 = rb2 + rw2 @ elu(r1)
    ull r2a[8], r2b[8];
    load_bias2<16>(r2a, r2b, s + S_RB2);
#pragma unroll
    for (int i = 0; i < 16; ++i) {
        float alo, ahi, blo, bhi;
        unpack2(r1a[i], alo, ahi);
        unpack2(r1b[i], blo, bhi);
        fma_row2<16>(r2a, r2b, s + S_R2T + (2 * i) * 16,     bcast2(elu1(alo)), bcast2(elu1(blo)));
        fma_row2<16>(r2a, r2b, s + S_R2T + (2 * i + 1) * 16, bcast2(elu1(ahi)), bcast2(elu1(bhi)));
    }
    float r2eA[16], r2eB[16];
#pragma unroll
    for (int i = 0; i < 8; ++i) {
        float lo, hi;
        unpack2(r2a[i], lo, hi); r2eA[2 * i] = elu1(lo); r2eA[2 * i + 1] = elu1(hi);
        unpack2(r2b[i], lo, hi); r2eB[2 * i] = elu1(lo); r2eB[2 * i + 1] = elu1(hi);
    }
#pragma unroll
    for (int c = 0; c < 3; ++c) {
        float aA = s[S_RB3 + c], aB = aA;
#pragma unroll
        for (int k = 0; k < 16; ++k) {
            float wv = s[S_RW3 + c * 16 + k];
            aA = fmaf(r2eA[k], wv, aA);
            aB = fmaf(r2eB[k], wv, aB);
        }
        out_rgb[(size_t)p0 * 3 + c] = 1.f / (1.f + __expf(-aA));
        out_rgb[(size_t)p1 * 3 + c] = 1.f / (1.f + __expf(-aB));
    }
#undef FA
#undef FB
}

extern "C" void kernel_launch(void* const* d_in, const int* in_sizes, int n_in,
                              void* d_out, int out_size)
{
    const float* rgb = (const float*)d_in[0];
    const float* bw1 = (const float*)d_in[1];
    const float* bb1 = (const float*)d_in[2];
    const float* bw2 = (const float*)d_in[3];
    const float* bb2 = (const float*)d_in[4];
    const float* vw1 = (const float*)d_in[5];
    const float* vb1 = (const float*)d_in[6];
    const float* vw2 = (const float*)d_in[7];
    const float* vb2 = (const float*)d_in[8];
    const float* rw1 = (const float*)d_in[9];
    const float* rb1 = (const float*)d_in[10];
    const float* rw2 = (const float*)d_in[11];
    const float* rb2 = (const float*)d_in[12];
    const float* rw3 = (const float*)d_in[13];
    const float* rb3 = (const float*)d_in[14];

    const int P = in_sizes[0] / 105;                  // 524288
    float* out_in  = (float*)d_out;                   // rgb_in : P*9
    float* out_rgb = (float*)d_out + (size_t)P * 9;   // rgb_out: P*3

    // K0: input transpose + rgb_in
    k_prep<<<P / 32, 256>>>(rgb, out_in, P);

    // K1: fused MLP
    cudaFuncSetAttribute(k_main, cudaFuncAttributeMaxDynamicSharedMemorySize, SMEM_BYTES);
    k_main<<<P / PTS_PER_BLOCK, THREADS, SMEM_BYTES>>>(
        bw1, bb1, bw2, bb2, vw1, vb1, vw2, vb2,
        rw1, rb1, rw2, rb2, rw3, rb3, out_rgb, P);
}

// round 7
// speedup vs baseline: 1.2651x; 1.2651x over previous
#include <cuda_runtime.h>

#define THREADS 256

// ---- shared-memory layout (floats) ----
#define S_W1T   0        // [105][64]  bw1 transposed  (6720)
#define S_B1    6720     // [64]
#define S_W2T   6784     // [64][32]   bw2 transposed  (2048)
#define S_B2    8832     // [32]
#define S_V1T   8864     // [32][32]   vw1 transposed, pre-scaled by 1/3 (1024)
#define S_VB1   9888     // [32]
#define S_V2T   9920     // [32][32]   vw2 transposed (1024)
#define S_VB2   10944    // [32]
#define S_R1T   10976    // [96][32]   rw1 transposed (3072)
#define S_RB1   14048    // [32]
#define S_R2T   14080    // [32][16]   rw2 transposed (512)
#define S_RB2   14592    // [16]
#define S_RW3   14608    // [3][16]    rw3 as-is (48)
#define S_RB3   14656    // [4]
#define S_WEND  14660
// r1 park: 16 ull slots x 256 threads = 8192 floats (32KB)
#define S_R1S   14660
#define S_TOT   (14660 + 8192)
#define SMEM_BYTES (S_TOT * 4)     // 91408 B -> 2 blocks/SM

#define P_CONST 524288

typedef unsigned long long ull;

// global scratch (module-static; allocation-free at kernel time)
__device__ float g_scr[(size_t)P_CONST * 105];        // input, interleaved [P/32][105][32]
__device__ ull   g1_scr[(size_t)32 * P_CONST];        // g1: slot j of point p at [j*P + p] (134MB)

__device__ __forceinline__ float elu1(float x) {
    return x > 0.f ? x : (__expf(x) - 1.f);
}
__device__ __forceinline__ void ffma2(ull &d, ull a, ull b) {
    asm("fma.rn.f32x2 %0, %1, %2, %0;" : "+l"(d) : "l"(a), "l"(b));
}
__device__ __forceinline__ void add2(ull &d, ull a) {
    asm("add.rn.f32x2 %0, %0, %1;" : "+l"(d) : "l"(a));
}
__device__ __forceinline__ ull bcast2(float c) {
    ull v; asm("mov.b64 %0, {%1, %2};" : "=l"(v) : "f"(c), "f"(c)); return v;
}
__device__ __forceinline__ ull pack2(float lo, float hi) {
    ull v; asm("mov.b64 %0, {%1, %2};" : "=l"(v) : "f"(lo), "f"(hi)); return v;
}
__device__ __forceinline__ void unpack2(ull v, float &lo, float &hi) {
    asm("mov.b64 {%0, %1}, %2;" : "=f"(lo), "=f"(hi) : "l"(v));
}

// acc[OUT/2] += c2 (*) row[0..OUT)   — row is SMEM, 16B-aligned (broadcast LDS.128)
template<int OUT>
__device__ __forceinline__ void fma_row(ull* acc, const float* row, ull c2) {
    const ulonglong2* wp = reinterpret_cast<const ulonglong2*>(row);
#pragma unroll
    for (int q = 0; q < OUT / 4; ++q) {
        ulonglong2 w = wp[q];
        ffma2(acc[2 * q],     c2, w.x);
        ffma2(acc[2 * q + 1], c2, w.y);
    }
}
template<int OUT>
__device__ __forceinline__ void load_bias(ull* acc, const float* b) {
    const ulonglong2* bp = reinterpret_cast<const ulonglong2*>(b);
#pragma unroll
    for (int q = 0; q < OUT / 4; ++q) {
        ulonglong2 w = bp[q];
        acc[2 * q]     = w.x;
        acc[2 * q + 1] = w.y;
    }
}

// ================= K0: transpose input to [P/32][105][32] + emit rgb_in ==========
__global__ __launch_bounds__(256, 4)
void k_prep(const float* __restrict__ rgb, float* __restrict__ out_in, int P)
{
    __shared__ float st[32 * 105];
    const int g = blockIdx.x;             // point group (32 points)
    const int tid = threadIdx.x;

    const float4* src4 = reinterpret_cast<const float4*>(rgb + (size_t)g * 3360);
    float4* st4 = reinterpret_cast<float4*>(st);
#pragma unroll
    for (int i = tid; i < 840; i += 256) st4[i] = src4[i];
    __syncthreads();

    float* dst = g_scr + (size_t)g * 105 * 32;
#pragma unroll
    for (int i = tid; i < 3360; i += 256) {
        int j = i >> 5, lane = i & 31;
        dst[i] = st[lane * 105 + j];
    }
    for (int i = tid; i < 288; i += 256) {
        int pl = i / 9, r = i % 9, v = r / 3, k = r % 3;
        out_in[((size_t)g * 32 + pl) * 9 + r] = st[pl * 105 + v * 35 + k];
    }
}

// ================= K1: fused MLP, 1 point/thread, 2 blocks/SM (16 warps) =========
__global__ __launch_bounds__(THREADS, 2)
void k_main(
    const float* __restrict__ bw1, const float* __restrict__ bb1,
    const float* __restrict__ bw2, const float* __restrict__ bb2,
    const float* __restrict__ vw1, const float* __restrict__ vb1,
    const float* __restrict__ vw2, const float* __restrict__ vb2,
    const float* __restrict__ rw1, const float* __restrict__ rb1,
    const float* __restrict__ rw2, const float* __restrict__ rb2,
    const float* __restrict__ rw3, const float* __restrict__ rb3,
    float* __restrict__ out_rgb, int P)
{
    extern __shared__ float s[];
    const int tid = threadIdx.x;

    // ---- stage weights (transposed) ----
    for (int i = tid; i < 6720; i += THREADS) { int k = i >> 6, j = i & 63; s[S_W1T + i] = bw1[j * 105 + k]; }
    for (int i = tid; i < 64;   i += THREADS) s[S_B1 + i] = bb1[i];
    for (int i = tid; i < 2048; i += THREADS) { int k = i >> 5, j = i & 31; s[S_W2T + i] = bw2[j * 64 + k]; }
    for (int i = tid; i < 32;   i += THREADS) s[S_B2 + i] = bb2[i];
    for (int i = tid; i < 1024; i += THREADS) { int k = i >> 5, j = i & 31; s[S_V1T + i] = vw1[j * 32 + k] * (1.f / 3.f); }
    for (int i = tid; i < 32;   i += THREADS) s[S_VB1 + i] = vb1[i];
    for (int i = tid; i < 1024; i += THREADS) { int k = i >> 5, j = i & 31; s[S_V2T + i] = vw2[j * 32 + k]; }
    for (int i = tid; i < 32;   i += THREADS) s[S_VB2 + i] = vb2[i];
    for (int i = tid; i < 3072; i += THREADS) { int k = i >> 5, j = i & 31; s[S_R1T + i] = rw1[j * 96 + k]; }
    for (int i = tid; i < 32;   i += THREADS) s[S_RB1 + i] = rb1[i];
    for (int i = tid; i < 512;  i += THREADS) { int k = i >> 4, j = i & 15; s[S_R2T + i] = rw2[j * 32 + k]; }
    for (int i = tid; i < 16;   i += THREADS) s[S_RB2 + i] = rb2[i];
    for (int i = tid; i < 48;   i += THREADS) s[S_RW3 + i] = rw3[i];
    for (int i = tid; i < 4;    i += THREADS) s[S_RB3 + i] = (i < 3) ? rb3[i] : 0.f;
    __syncthreads();

    const int lane = tid & 31;
    const int p = blockIdx.x * THREADS + tid;           // one point per thread
    // input: element j of point p at g_scr[(p>>5)*3360 + j*32 + (p&31)]
    const float* f = g_scr + ((size_t)(p >> 5)) * 3360 + lane;
#define F(j) __ldg(f + (j) * 32)

    ull* g1p = g1_scr + p;                              // slot j at g1p[j*P_CONST]
    ull* r1s = reinterpret_cast<ull*>(s + S_R1S);       // slot j at r1s[j*THREADS + tid]

    // ---- init r1 park from bias ----
    {
        const ulonglong2* bp = reinterpret_cast<const ulonglong2*>(s + S_RB1);
#pragma unroll
        for (int q = 0; q < 8; ++q) {
            ulonglong2 b = bp[q];
            r1s[(2 * q) * THREADS + tid]     = b.x;
            r1s[(2 * q + 1) * THREADS + tid] = b.y;
        }
    }

    // ---- phase 0: stats + g1 = bb1 + W1[:,:70] @ [mean,var]; park in global ----
    {
        ull g1[32];
        load_bias<64>(g1, s + S_B1);
#pragma unroll 5
        for (int k = 0; k < 35; ++k) {
            float a = F(k), b = F(35 + k), c = F(70 + k);
            float m = (a + b + c) * (1.f / 3.f);
            float q = fmaf(-m, m, fmaf(a, a, fmaf(b, b, c * c)) * (1.f / 3.f));
            fma_row<64>(g1, s + S_W1T + k * 64,        bcast2(m));
            fma_row<64>(g1, s + S_W1T + (35 + k) * 64, bcast2(q));
        }
#pragma unroll
        for (int j = 0; j < 32; ++j)
            g1p[(size_t)j * P_CONST] = g1[j];
    }

    // ---- per-view MLP ----
#pragma unroll 1
    for (int v = 0; v < 3; ++v) {
        ull h2[16];
        load_bias<32>(h2, s + S_B2);

        // layer1 in 32-neuron halves; g1 half prefetched, added at end (latency hidden)
#pragma unroll 1
        for (int h = 0; h < 2; ++h) {
            ull gp[16];
#pragma unroll
            for (int j = 0; j < 16; ++j)
                gp[j] = g1p[(size_t)(h * 16 + j) * P_CONST];   // independent LDG.64s, consumed late

            ull h1[16];
#pragma unroll
            for (int j = 0; j < 16; ++j) h1[j] = 0ULL;         // (+0.0f, +0.0f)
#pragma unroll 5
            for (int k = 0; k < 35; ++k)
                fma_row<32>(h1, s + S_W1T + (70 + k) * 64 + h * 32, bcast2(F(v * 35 + k)));
#pragma unroll
            for (int j = 0; j < 16; ++j) add2(h1[j], gp[j]);   // h1 = rows + g1(incl bias)

            // layer2 partial: rows k2 = h*32 .. h*32+31 consume elu(h1)
#pragma unroll
            for (int i = 0; i < 16; ++i) {
                float lo, hi; unpack2(h1[i], lo, hi);
                fma_row<32>(h2, s + S_W2T + (h * 32 + 2 * i) * 32,     bcast2(elu1(lo)));
                fma_row<32>(h2, s + S_W2T + (h * 32 + 2 * i + 1) * 32, bcast2(elu1(hi)));
            }
        }
        // h2e = elu(h2) in place (t1 input AND residual)
#pragma unroll
        for (int i = 0; i < 16; ++i) {
            float lo, hi; unpack2(h2[i], lo, hi);
            h2[i] = pack2(elu1(lo), elu1(hi));
        }

        // t1 = vb1 + (vw1/3) @ h2e
        ull t1[16];
        load_bias<32>(t1, s + S_VB1);
#pragma unroll
        for (int i = 0; i < 16; ++i) {
            float lo, hi; unpack2(h2[i], lo, hi);
            fma_row<32>(t1, s + S_V1T + (2 * i) * 32,     bcast2(lo));
            fma_row<32>(t1, s + S_V1T + (2 * i + 1) * 32, bcast2(hi));
        }
        // t2 = vb2 + vw2 @ elu(t1)   (elu fused at use; t1 dies)
        ull t2[16];
        load_bias<32>(t2, s + S_VB2);
#pragma unroll
        for (int i = 0; i < 16; ++i) {
            float lo, hi; unpack2(t1[i], lo, hi);
            fma_row<32>(t2, s + S_V2T + (2 * i) * 32,     bcast2(elu1(lo)));
            fma_row<32>(t2, s + S_V2T + (2 * i + 1) * 32, bcast2(elu1(hi)));
        }

        // fold x = h2e + elu(t2) into r1 (parked in smem)
        ull r1[16];
#pragma unroll
        for (int j = 0; j < 16; ++j) r1[j] = r1s[j * THREADS + tid];
#pragma unroll
        for (int i = 0; i < 16; ++i) {
            float tlo, thi, hlo, hhi;
            unpack2(t2[i], tlo, thi);
            unpack2(h2[i], hlo, hhi);
            fma_row<32>(r1, s + S_R1T + (v * 32 + 2 * i) * 32,     bcast2(hlo + elu1(tlo)));
            fma_row<32>(r1, s + S_R1T + (v * 32 + 2 * i + 1) * 32, bcast2(hhi + elu1(thi)));
        }
#pragma unroll
        for (int j = 0; j < 16; ++j) r1s[j * THREADS + tid] = r1[j];
    }

    // ---- head: r2 = rb2 + rw2 @ elu(r1) ----
    ull r2[8];
    load_bias<16>(r2, s + S_RB2);
#pragma unroll
    for (int i = 0; i < 16; ++i) {
        ull r1i = r1s[i * THREADS + tid];
        float lo, hi; unpack2(r1i, lo, hi);
        fma_row<16>(r2, s + S_R2T + (2 * i) * 16,     bcast2(elu1(lo)));
        fma_row<16>(r2, s + S_R2T + (2 * i + 1) * 16, bcast2(elu1(hi)));
    }
    float r2e[16];
#pragma unroll
    for (int i = 0; i < 8; ++i) {
        float lo, hi; unpack2(r2[i], lo, hi);
        r2e[2 * i]     = elu1(lo);
        r2e[2 * i + 1] = elu1(hi);
    }
#pragma unroll
    for (int c = 0; c < 3; ++c) {
        float a = s[S_RB3 + c];
#pragma unroll
        for (int k = 0; k < 16; ++k)
            a = fmaf(r2e[k], s[S_RW3 + c * 16 + k], a);
        out_rgb[(size_t)p * 3 + c] = 1.f / (1.f + __expf(-a));
    }
#undef F
}

extern "C" void kernel_launch(void* const* d_in, const int* in_sizes, int n_in,
                              void* d_out, int out_size)
{
    const float* rgb = (const float*)d_in[0];
    const float* bw1 = (const float*)d_in[1];
    const float* bb1 = (const float*)d_in[2];
    const float* bw2 = (const float*)d_in[3];
    const float* bb2 = (const float*)d_in[4];
    const float* vw1 = (const float*)d_in[5];
    const float* vb1 = (const float*)d_in[6];
    const float* vw2 = (const float*)d_in[7];
    const float* vb2 = (const float*)d_in[8];
    const float* rw1 = (const float*)d_in[9];
    const float* rb1 = (const float*)d_in[10];
    const float* rw2 = (const float*)d_in[11];
    const float* rb2 = (const float*)d_in[12];
    const float* rw3 = (const float*)d_in[13];
    const float* rb3 = (const float*)d_in[14];

    const int P = in_sizes[0] / 105;                  // 524288
    float* out_in  = (float*)d_out;                   // rgb_in : P*9
    float* out_rgb = (float*)d_out + (size_t)P * 9;   // rgb_out: P*3

    // K0: input transpose + rgb_in
    k_prep<<<P / 32, 256>>>(rgb, out_in, P);

    // K1: fused MLP
    cudaFuncSetAttribute(k_main, cudaFuncAttributeMaxDynamicSharedMemorySize, SMEM_BYTES);
    k_main<<<P / THREADS, THREADS, SMEM_BYTES>>>(
        bw1, bb1, bw2, bb2, vw1, vb1, vw2, vb2,
        rw1, rb1, rw2, rb2, rw3, rb3, out_rgb, P);
}